// round 7
// baseline (speedup 1.0000x reference)
#include <cuda_runtime.h>
#include <math.h>
#include <stdint.h>

// ---------------------------------------------------------------------------
// FNO2d: B=16, Cin=5, S=128, W=64 ch, M=16 modes, D=4 layers, PAD=9 -> H=137
// Transforms: register-blocked fp32 DFT GEMMs.
// conv1x1 / head GEMMs: mma.sync m16n8k8 tf32 (3-term error split), fp32 acc.
// ---------------------------------------------------------------------------

#define NB 16
#define NC 64
#define NH 137
#define NPIX (137*137)      // 18769
#define NM 16
#define NKX 32
#define ND 4
#define NBC (NB*NC)         // 1024

static __device__ __align__(16) float g_x[NBC*NPIX];       // field [bc][x*137+y]
static __device__ __align__(16) float g_a[NBC*NPIX];       // scratch
static __device__ __align__(16) float g_Y[NBC*NH*32];      // col DFT [bc][x][2m+p]
static __device__ __align__(16) float g_Z[512*2*NBC];      // spectrum [kk][p][bc]
static __device__ __align__(16) float g_S[NBC*1024];       // mixed [bo][kx][ky][p]
static __device__ __align__(16) float g_U[NBC*32*NH];      // inv-row [bo][2ky+p][x]
static __device__ __align__(16) float g_wm[ND*512*2*4096]; // [d][kk][p][i*64+o]
static __device__ __align__(16) float g_Ft[NH*32];         // fwd col [y][2m+p]
static __device__ __align__(16) float g_Gt[NH*64];         // fwd row [x][2kx+p]
static __device__ __align__(16) float g_Et[32*2*NH];       // inv row [kx][2x+p]
static __device__ __align__(16) float g_Tt[NH*32];         // inv col [y][2ky+p]

__device__ __forceinline__ float gelu_f(float v) {
    return 0.5f * v * (1.0f + erff(v * 0.70710678118654752440f));
}

// ====================== tf32 mma.sync machinery ============================
__device__ __forceinline__ uint32_t f2tf(float v) {
    uint32_t r;
    asm("cvt.rna.tf32.f32 %0, %1;" : "=r"(r) : "f"(v));
    return r;
}
__device__ __forceinline__ void mma1688(float* d,
                                        uint32_t a0, uint32_t a1, uint32_t a2, uint32_t a3,
                                        uint32_t b0, uint32_t b1) {
    asm volatile(
        "mma.sync.aligned.m16n8k8.row.col.f32.tf32.tf32.f32 "
        "{%0,%1,%2,%3}, {%4,%5,%6,%7}, {%8,%9}, {%0,%1,%2,%3};"
        : "+f"(d[0]), "+f"(d[1]), "+f"(d[2]), "+f"(d[3])
        : "r"(a0), "r"(a1), "r"(a2), "r"(a3), "r"(b0), "r"(b1));
}

// split v = hi + lo (tf32 parts), stored as float bit-patterns
__device__ __forceinline__ void tf_split(float v, float& h, float& l) {
    uint32_t hb = f2tf(v);
    float hf = __uint_as_float(hb);
    h = hf;
    l = __uint_as_float(f2tf(v - hf));
}

// Stage [64pix x 64ch] from channel-major plane into sAh/sAl [pix][ch] (pitch 65)
__device__ __forceinline__ void stageA_plane(float* sAh, float* sAl,
                                             const float* __restrict__ plane,
                                             int p0, int tid) {
    for (int idx = tid; idx < 4096; idx += 128) {
        int ch = idx >> 6, pix = idx & 63;
        int p = p0 + pix;
        float v = 0.f;
        if (p < NPIX) v = plane[(size_t)ch*NPIX + p];
        float h, l; tf_split(v, h, l);
        sAh[pix*65 + ch] = h;
        sAl[pix*65 + ch] = l;
    }
}

// Stage [64o x 64i] row-major weight into sB [k=i][n=o] (pitch 65)
__device__ __forceinline__ void stageB_w(float* sBh, float* sBl,
                                         const float* __restrict__ ws, int tid) {
    for (int idx = tid; idx < 4096; idx += 128) {
        int o = idx >> 6, i = idx & 63;
        float v = ws[idx];
        float h, l; tf_split(v, h, l);
        sBh[i*65 + o] = h;
        sBl[i*65 + o] = l;
    }
}

// 16x64 (per warp) x K=64 GEMM accumulate: 3-term tf32 split
__device__ __forceinline__ void gemm64(float acc[8][4],
                                       const float* sAh, const float* sAl,
                                       const float* sBh, const float* sBl,
                                       int lane) {
    int g = lane >> 2, tg = lane & 3;
    const float* arh = sAh + g*65;
    const float* arl = sAl + g*65;
    #pragma unroll
    for (int s = 0; s < 8; s++) {
        int ka = s*8 + tg;
        uint32_t a0h = __float_as_uint(arh[ka]);
        uint32_t a1h = __float_as_uint(arh[8*65 + ka]);
        uint32_t a2h = __float_as_uint(arh[ka + 4]);
        uint32_t a3h = __float_as_uint(arh[8*65 + ka + 4]);
        uint32_t a0l = __float_as_uint(arl[ka]);
        uint32_t a1l = __float_as_uint(arl[8*65 + ka]);
        uint32_t a2l = __float_as_uint(arl[ka + 4]);
        uint32_t a3l = __float_as_uint(arl[8*65 + ka + 4]);
        #pragma unroll
        for (int n = 0; n < 8; n++) {
            uint32_t b0h = __float_as_uint(sBh[ka*65 + n*8 + g]);
            uint32_t b1h = __float_as_uint(sBh[(ka+4)*65 + n*8 + g]);
            uint32_t b0l = __float_as_uint(sBl[ka*65 + n*8 + g]);
            uint32_t b1l = __float_as_uint(sBl[(ka+4)*65 + n*8 + g]);
            mma1688(acc[n], a0h, a1h, a2h, a3h, b0h, b1h);
            mma1688(acc[n], a0h, a1h, a2h, a3h, b0l, b1l);
            mma1688(acc[n], a0l, a1l, a2l, a3l, b0h, b1h);
        }
    }
}

// ---------------- twiddle tables (double-precision sincos) -----------------
__global__ void k_tables() {
    int idx = blockIdx.x * blockDim.x + threadIdx.x;
    if (idx >= NKX * NH) return;
    int j = idx / NH, t = idx - j * NH;
    int gk = (j < NM) ? j : (NH - NKX + j);
    const double TWO_PI = 6.283185307179586476925286766559;
    double th = TWO_PI * (double)gk * (double)t / (double)NH;
    double s, c;
    sincos(th, &s, &c);
    g_Gt[t*64 + 2*j]     = (float)c;
    g_Gt[t*64 + 2*j + 1] = (float)(-s);
    g_Et[j*(2*NH) + 2*t]     = (float)c;
    g_Et[j*(2*NH) + 2*t + 1] = (float)(s);
    if (j < NM) {
        g_Ft[t*32 + 2*j]     = (float)c;
        g_Ft[t*32 + 2*j + 1] = (float)(-s);
        double wgt = ((j == 0) ? 1.0 : 2.0) / ((double)NH * (double)NH);
        g_Tt[t*32 + 2*j]     = (float)(wgt * c);
        g_Tt[t*32 + 2*j + 1] = (float)(-wgt * s);
    }
}

// ------------- spectral weight transpose: [d][p][i][o][mx][my] -> wm -------
__global__ void k_wt(const float* __restrict__ sw1, const float* __restrict__ sw2) {
    __shared__ float tile[32][33];
    int d   = blockIdx.z >> 2;
    int p   = (blockIdx.z >> 1) & 1;
    int arr = blockIdx.z & 1;
    const float* src = (arr ? sw2 : sw1) + (size_t)(d*2 + p) * 4096 * 256;
    int mxy = blockIdx.x * 32 + threadIdx.x;
    int io  = blockIdx.y * 32 + threadIdx.y;
    tile[threadIdx.y][threadIdx.x] = src[(size_t)io * 256 + mxy];
    __syncthreads();
    int mxy2 = blockIdx.x * 32 + threadIdx.y;
    int io2  = blockIdx.y * 32 + threadIdx.x;
    g_wm[((size_t)(d*512 + arr*256 + mxy2) * 2 + p) * 4096 + io2] = tile[threadIdx.x][threadIdx.y];
}

// ---------------- embed: concat grids, project 7->64, zero-pad -------------
__global__ __launch_bounds__(160) void k_embed(const float* __restrict__ xin,
                                               const float* __restrict__ pw,
                                               const float* __restrict__ pb) {
    __shared__ float spw[448];
    __shared__ float spb[64];
    int tid = threadIdx.x;
    for (int j = tid; j < 448; j += 160) spw[j] = pw[j];
    if (tid < 64) spb[tid] = pb[tid];
    __syncthreads();
    int b = blockIdx.y, x = blockIdx.x, y = tid;
    if (y >= NH) return;
    bool interior = (x < 128 && y < 128);
    float c[5]; float gx = 0.f, gy = 0.f;
    if (interior) {
        const float* src = xin + ((size_t)(b*5) * 128 + x) * 128 + y;
        #pragma unroll
        for (int i = 0; i < 5; i++) c[i] = src[(size_t)i * 128 * 128];
        const float step = 1.0f / 127.0f;
        gx = x * step; gy = y * step;
    }
    float* dst = g_x + ((size_t)(b*64) * NH + x) * NH + y;
    #pragma unroll 4
    for (int dd = 0; dd < 64; dd++) {
        float s = 0.f;
        if (interior) {
            s = spb[dd];
            #pragma unroll
            for (int i = 0; i < 5; i++) s += c[i] * spw[i*64 + dd];
            s += gx * spw[5*64 + dd] + gy * spw[6*64 + dd];
        }
        dst[(size_t)dd * NPIX] = s;
    }
}

// ------- forward column DFT over y: GEMM C[48x x 32] = X[48x137] F[137x32] ---
__global__ __launch_bounds__(128) void k_coldft() {
    __shared__ __align__(16) float sx[NH*49];   // [y][xr], scalar reads only
    int bc = blockIdx.y;
    int x0 = blockIdx.x * 48;
    int tid = threadIdx.x;
    const float* xin = g_x + (size_t)bc * NPIX;
    for (int idx = tid; idx < 48*NH; idx += 128) {
        int xr = idx / NH, y = idx - xr*NH;
        float v = (x0 + xr < NH) ? xin[(size_t)(x0+xr)*NH + y] : 0.f;
        sx[y*49 + xr] = v;
    }
    __syncthreads();
    int tx = tid & 7, ty = tid >> 3;
    int r0 = ty*3, c0 = tx*4;
    float4 a0 = {0,0,0,0}, a1 = {0,0,0,0}, a2 = {0,0,0,0};
    #pragma unroll 2
    for (int y = 0; y < NH; y++) {
        float4 f = *(const float4*)&g_Ft[y*32 + c0];   // L1-resident
        float v0 = sx[y*49 + r0];
        float v1 = sx[y*49 + r0 + 1];
        float v2 = sx[y*49 + r0 + 2];
        a0.x += v0*f.x; a0.y += v0*f.y; a0.z += v0*f.z; a0.w += v0*f.w;
        a1.x += v1*f.x; a1.y += v1*f.y; a1.z += v1*f.z; a1.w += v1*f.w;
        a2.x += v2*f.x; a2.y += v2*f.y; a2.z += v2*f.z; a2.w += v2*f.w;
    }
    int r = x0 + r0;
    if (r < NH) {
        float* gy = &g_Y[((size_t)bc*NH + r)*32 + c0];
        gy[0] = a0.x; gy[1] = a0.y; gy[2] = a0.z; gy[3] = a0.w;
    }
    if (r + 1 < NH) {
        float* gy = &g_Y[((size_t)bc*NH + r + 1)*32 + c0];
        gy[0] = a1.x; gy[1] = a1.y; gy[2] = a1.z; gy[3] = a1.w;
    }
    if (r + 2 < NH) {
        float* gy = &g_Y[((size_t)bc*NH + r + 2)*32 + c0];
        gy[0] = a2.x; gy[1] = a2.y; gy[2] = a2.z; gy[3] = a2.w;
    }
}

// ------- forward row DFT over x: C[16ky x 32kx] complex, K=137 -------------
__global__ __launch_bounds__(128) void k_rowdft() {
    __shared__ __align__(16) float ys[NH*36];   // [x][2ky+p] pad 36
    int bc = blockIdx.x;
    int tid = threadIdx.x;
    for (int idx = tid; idx < NH*32; idx += 128) {
        int x = idx >> 5, c = idx & 31;
        ys[x*36 + c] = g_Y[((size_t)bc*NH + x)*32 + c];
    }
    __syncthreads();
    int tx = tid & 31;
    int ty = tid >> 5;
    float re[4] = {0,0,0,0}, im[4] = {0,0,0,0};
    #pragma unroll 2
    for (int x = 0; x < NH; x++) {
        const float4* yp = (const float4*)&ys[x*36 + ty*8];
        float4 yA = yp[0];
        float4 yB = yp[1];
        float gc = g_Gt[x*64 + 2*tx];
        float gs = g_Gt[x*64 + 2*tx + 1];
        re[0] += yA.x*gc - yA.y*gs;  im[0] += yA.x*gs + yA.y*gc;
        re[1] += yA.z*gc - yA.w*gs;  im[1] += yA.z*gs + yA.w*gc;
        re[2] += yB.x*gc - yB.y*gs;  im[2] += yB.x*gs + yB.y*gc;
        re[3] += yB.z*gc - yB.w*gs;  im[3] += yB.z*gs + yB.w*gc;
    }
    #pragma unroll
    for (int j = 0; j < 4; j++) {
        int ky = ty*4 + j;
        size_t base = (size_t)((tx*16 + ky)*2)*NBC + bc;
        g_Z[base]       = re[j];
        g_Z[base + NBC] = im[j];
    }
}

// ---------------- spectral channel mix: complex 64x64 per (kx,ky) ----------
__global__ __launch_bounds__(256) void k_mix(int d) {
    __shared__ float zr[1024], zi[1024];
    __shared__ float wr[4096], wi[4096];
    int kk = blockIdx.x;
    int tid = threadIdx.x;
    const float* wb = g_wm + ((size_t)(d*512 + kk) * 2) * 4096;
    for (int idx = tid; idx < 1024; idx += 256) {
        zr[idx] = g_Z[(size_t)(kk*2)*NBC + idx];
        zi[idx] = g_Z[(size_t)(kk*2 + 1)*NBC + idx];
    }
    for (int idx = tid; idx < 4096; idx += 256) {
        wr[idx] = wb[idx];
        wi[idx] = wb[4096 + idx];
    }
    __syncthreads();
    int kx = kk >> 4, ky = kk & 15;
    int o = tid & 63, bg = tid >> 6;
    float re[4] = {0,0,0,0}, im[4] = {0,0,0,0};
    #pragma unroll 2
    for (int i = 0; i < 64; i++) {
        float wrv = wr[i*64 + o], wiv = wi[i*64 + o];
        #pragma unroll
        for (int jb = 0; jb < 4; jb++) {
            int b = bg*4 + jb;
            float a = zr[b*64 + i], bb = zi[b*64 + i];
            re[jb] += a*wrv - bb*wiv;
            im[jb] += a*wiv + bb*wrv;
        }
    }
    #pragma unroll
    for (int jb = 0; jb < 4; jb++) {
        size_t off = (size_t)((bg*4 + jb)*64 + o)*1024 + kx*32 + ky*2;
        g_S[off] = re[jb]; g_S[off + 1] = im[jb];
    }
}

// ------- inverse row transform: per x, all 16 ky complex, K=32 kx ----------
__global__ __launch_bounds__(160) void k_invrow() {
    __shared__ __align__(16) float ss[1024];        // [kx][2ky+p]
    int bo = blockIdx.x, tid = threadIdx.x;
    for (int idx = tid; idx < 1024; idx += 160) ss[idx] = g_S[(size_t)bo*1024 + idx];
    __syncthreads();
    int x = tid;
    if (x >= NH) return;
    float re[16], im[16];
    #pragma unroll
    for (int j = 0; j < 16; j++) { re[j] = 0.f; im[j] = 0.f; }
    for (int k = 0; k < 32; k++) {
        float2 e = *(const float2*)&g_Et[k*(2*NH) + 2*x];    // L1-resident
        #pragma unroll
        for (int ky = 0; ky < 16; ky++) {
            float2 s = *(const float2*)&ss[k*32 + 2*ky];     // broadcast
            re[ky] += s.x*e.x - s.y*e.y;
            im[ky] += s.x*e.y + s.y*e.x;
        }
    }
    float* ub = g_U + (size_t)bo*32*NH;
    #pragma unroll
    for (int ky = 0; ky < 16; ky++) {
        ub[(2*ky)*NH + x]   = re[ky];
        ub[(2*ky+1)*NH + x] = im[ky];
    }
}

// ------- inverse column transform: u[32] in regs, lane=y coalesced stores --
__global__ __launch_bounds__(256) void k_invcol() {
    __shared__ __align__(16) float ts[NH*36];   // [y][2ky+p] pad 36
    int bo = blockIdx.y;
    int tid = threadIdx.x;
    for (int idx = tid; idx < NH*32; idx += 256) {
        int y = idx >> 5, c = idx & 31;
        ts[y*36 + c] = g_Tt[idx];
    }
    __syncthreads();
    int ly = tid & 31, xg = tid >> 5;
    int x = blockIdx.x * 8 + xg;
    if (x >= NH) return;
    const float* ub = g_U + (size_t)bo*32*NH;
    float u[32];
    #pragma unroll
    for (int k = 0; k < 32; k++) u[k] = ub[k*NH + x];
    float* dst = g_a + (size_t)bo*NPIX + (size_t)x*NH;
    for (int y = ly; y < NH; y += 32) {
        const float4* t4 = (const float4*)&ts[y*36];
        float acc = 0.f;
        #pragma unroll
        for (int kh = 0; kh < 8; kh++) {
            float4 t = t4[kh];
            acc += u[4*kh]*t.x + u[4*kh+1]*t.y + u[4*kh+2]*t.z + u[4*kh+3]*t.w;
        }
        dst[y] = acc;
    }
}

// ================= tf32 mma conv1x1 kernels ================================
// dyn smem (floats): sAh[4160], sAl[4160], sBh[4160], sBl[4160], bias[64]
#define MLP_SMEMF (4160*4 + 64)

__global__ __launch_bounds__(128)
void k_mlp1_m(const float* __restrict__ w, const float* __restrict__ bias, int d) {
    extern __shared__ __align__(16) float sm[];
    float* sAh = sm;
    float* sAl = sm + 4160;
    float* sBh = sm + 8320;
    float* sBl = sm + 12480;
    float* sbias = sm + 16640;
    int tid = threadIdx.x, lane = tid & 31, wp = tid >> 5;
    int b = blockIdx.y;
    int p0 = blockIdx.x * 64;
    float* plane = g_a + (size_t)b*64*NPIX;

    if (tid < 64) sbias[tid] = bias[d*64 + tid];
    stageA_plane(sAh, sAl, plane, p0, tid);
    stageB_w(sBh, sBl, w + (size_t)d*4096, tid);
    __syncthreads();

    float acc[8][4];
    #pragma unroll
    for (int n = 0; n < 8; n++)
        #pragma unroll
        for (int q = 0; q < 4; q++) acc[n][q] = 0.f;

    gemm64(acc, sAh + wp*16*65, sAl + wp*16*65, sBh, sBl, lane);

    int g = lane >> 2, tg = lane & 3;
    int pix0 = p0 + wp*16 + g, pix1 = pix0 + 8;
    #pragma unroll
    for (int n = 0; n < 8; n++) {
        int ch = n*8 + 2*tg;
        if (pix0 < NPIX) {
            plane[(size_t)ch*NPIX + pix0]     = gelu_f(acc[n][0] + sbias[ch]);
            plane[(size_t)(ch+1)*NPIX + pix0] = gelu_f(acc[n][1] + sbias[ch+1]);
        }
        if (pix1 < NPIX) {
            plane[(size_t)ch*NPIX + pix1]     = gelu_f(acc[n][2] + sbias[ch]);
            plane[(size_t)(ch+1)*NPIX + pix1] = gelu_f(acc[n][3] + sbias[ch+1]);
        }
    }
}

__global__ __launch_bounds__(128)
void k_mlp2_m(const float* __restrict__ w2, const float* __restrict__ b2,
              const float* __restrict__ wwp, const float* __restrict__ wbp, int d) {
    extern __shared__ __align__(16) float sm[];
    float* sAh = sm;
    float* sAl = sm + 4160;
    float* sBh = sm + 8320;
    float* sBl = sm + 12480;
    float* sbias = sm + 16640;
    int tid = threadIdx.x, lane = tid & 31, wp = tid >> 5;
    int b = blockIdx.y;
    int p0 = blockIdx.x * 64;
    float* planeA = g_a + (size_t)b*64*NPIX;   // x1
    float* planeX = g_x + (size_t)b*64*NPIX;   // residual in / output

    if (tid < 64) sbias[tid] = b2[d*64 + tid] + wbp[d*64 + tid];
    stageA_plane(sAh, sAl, planeA, p0, tid);
    stageB_w(sBh, sBl, w2 + (size_t)d*4096, tid);
    __syncthreads();

    float acc[8][4];
    #pragma unroll
    for (int n = 0; n < 8; n++)
        #pragma unroll
        for (int q = 0; q < 4; q++) acc[n][q] = 0.f;

    gemm64(acc, sAh + wp*16*65, sAl + wp*16*65, sBh, sBl, lane);
    __syncthreads();   // all warps done reading before restage

    stageA_plane(sAh, sAl, planeX, p0, tid);
    stageB_w(sBh, sBl, wwp + (size_t)d*4096, tid);
    __syncthreads();

    gemm64(acc, sAh + wp*16*65, sAl + wp*16*65, sBh, sBl, lane);

    int g = lane >> 2, tg = lane & 3;
    int pix0 = p0 + wp*16 + g, pix1 = pix0 + 8;
    #pragma unroll
    for (int n = 0; n < 8; n++) {
        int ch = n*8 + 2*tg;
        if (pix0 < NPIX) {
            planeX[(size_t)ch*NPIX + pix0]     = gelu_f(acc[n][0] + sbias[ch]);
            planeX[(size_t)(ch+1)*NPIX + pix0] = gelu_f(acc[n][1] + sbias[ch+1]);
        }
        if (pix1 < NPIX) {
            planeX[(size_t)ch*NPIX + pix1]     = gelu_f(acc[n][2] + sbias[ch]);
            planeX[(size_t)(ch+1)*NPIX + pix1] = gelu_f(acc[n][3] + sbias[ch+1]);
        }
    }
}

// ======= head: crop + q1(64->256) + gelu + q2(256->1), tf32 mma =============
// dyn smem (floats): sAh[4160], sAl[4160], sBh[4160], sBl[4160], sb1[256], s2[256]
#define HEAD_SMEMF (4160*4 + 512)

__global__ __launch_bounds__(128)
void k_head_m(const float* __restrict__ q1w, const float* __restrict__ q1b,
              const float* __restrict__ q2w, const float* __restrict__ q2b,
              float* __restrict__ out) {
    extern __shared__ __align__(16) float sm[];
    float* sAh = sm;
    float* sAl = sm + 4160;
    float* sBh = sm + 8320;
    float* sBl = sm + 12480;
    float* sb1 = sm + 16640;
    float* s2  = sm + 16896;
    int tid = threadIdx.x, lane = tid & 31, wp = tid >> 5;
    int b = blockIdx.y;
    int p0 = blockIdx.x * 64;                 // crop-pixel tile base (<16384)
    const float* plane = g_x + (size_t)b*64*NPIX;

    // stage A: 64 crop pixels x 64 ch
    for (int idx = tid; idx < 4096; idx += 128) {
        int ch = idx >> 6, j = idx & 63;
        int cp = p0 + j;
        int x = cp >> 7, y = cp & 127;
        float v = plane[(size_t)ch*NPIX + x*NH + y];
        float h, l; tf_split(v, h, l);
        sAh[j*65 + ch] = h;
        sAl[j*65 + ch] = l;
    }
    if (tid < 128) { sb1[tid] = q1b[tid]; sb1[128 + tid] = q1b[128 + tid]; }
    if (tid < 128) { s2[tid] = q2w[tid]; s2[128 + tid] = q2w[128 + tid]; }

    int g = lane >> 2, tg = lane & 3;
    float o0 = 0.f, o1 = 0.f;
    for (int chunk = 0; chunk < 4; chunk++) {
        __syncthreads();
        // stage B chunk: q1w rows [chunk*64, +64) -> sB[k=i][n=o_local]
        for (int idx = tid; idx < 4096; idx += 128) {
            int o = idx >> 6, i = idx & 63;
            float v = q1w[(size_t)(chunk*64 + o)*64 + i];
            float h, l; tf_split(v, h, l);
            sBh[i*65 + o] = h;
            sBl[i*65 + o] = l;
        }
        __syncthreads();
        float acc[8][4];
        #pragma unroll
        for (int n = 0; n < 8; n++)
            #pragma unroll
            for (int q = 0; q < 4; q++) acc[n][q] = 0.f;
        gemm64(acc, sAh + wp*16*65, sAl + wp*16*65, sBh, sBl, lane);
        #pragma unroll
        for (int n = 0; n < 8; n++) {
            int ch = chunk*64 + n*8 + 2*tg;
            o0 += s2[ch]   * gelu_f(acc[n][0] + sb1[ch]);
            o0 += s2[ch+1] * gelu_f(acc[n][1] + sb1[ch+1]);
            o1 += s2[ch]   * gelu_f(acc[n][2] + sb1[ch]);
            o1 += s2[ch+1] * gelu_f(acc[n][3] + sb1[ch+1]);
        }
    }
    // reduce over the 4 tig lanes
    o0 += __shfl_xor_sync(0xffffffffu, o0, 1);
    o0 += __shfl_xor_sync(0xffffffffu, o0, 2);
    o1 += __shfl_xor_sync(0xffffffffu, o1, 1);
    o1 += __shfl_xor_sync(0xffffffffu, o1, 2);
    if (tg == 0) {
        float qb = q2b[0];
        int pix0 = p0 + wp*16 + g;
        out[(size_t)b*16384 + pix0]     = o0 + qb;
        out[(size_t)b*16384 + pix0 + 8] = o1 + qb;
    }
}

// ---------------------------------------------------------------------------
extern "C" void kernel_launch(void* const* d_in, const int* in_sizes, int n_in,
                              void* d_out, int out_size) {
    const float* x   = (const float*)d_in[0];
    const float* p_w = (const float*)d_in[1];
    const float* p_b = (const float*)d_in[2];
    const float* sw1 = (const float*)d_in[3];
    const float* sw2 = (const float*)d_in[4];
    const float* m1w = (const float*)d_in[5];
    const float* m1b = (const float*)d_in[6];
    const float* m2w = (const float*)d_in[7];
    const float* m2b = (const float*)d_in[8];
    const float* wwp = (const float*)d_in[9];
    const float* wbp = (const float*)d_in[10];
    const float* q1w = (const float*)d_in[11];
    const float* q1b = (const float*)d_in[12];
    const float* q2w = (const float*)d_in[13];
    const float* q2b = (const float*)d_in[14];
    float* out = (float*)d_out;

    static int attr_done = 0;
    if (!attr_done) {
        cudaFuncSetAttribute(k_mlp1_m, cudaFuncAttributeMaxDynamicSharedMemorySize, MLP_SMEMF*4);
        cudaFuncSetAttribute(k_mlp2_m, cudaFuncAttributeMaxDynamicSharedMemorySize, MLP_SMEMF*4);
        cudaFuncSetAttribute(k_head_m, cudaFuncAttributeMaxDynamicSharedMemorySize, HEAD_SMEMF*4);
        attr_done = 1;
    }

    k_tables<<<18, 256>>>();
    k_wt<<<dim3(8, 128, 16), dim3(32, 32)>>>(sw1, sw2);
    k_embed<<<dim3(137, 16), 160>>>(x, p_w, p_b);

    const int mtiles = (NPIX + 63) / 64;   // 294
    for (int d = 0; d < ND; d++) {
        k_coldft<<<dim3(3, NBC), 128>>>();
        k_rowdft<<<NBC, 128>>>();
        k_mix<<<512, 256>>>(d);
        k_invrow<<<NBC, 160>>>();
        k_invcol<<<dim3(18, NBC), 256>>>();
        k_mlp1_m<<<dim3(mtiles, NB), 128, MLP_SMEMF*4>>>(m1w, m1b, d);
        k_mlp2_m<<<dim3(mtiles, NB), 128, MLP_SMEMF*4>>>(m2w, m2b, wwp, wbp, d);
    }

    k_head_m<<<dim3(256, NB), 128, HEAD_SMEMF*4>>>(q1w, q1b, q2w, q2b, out);
}

// round 9
// speedup vs baseline: 1.2356x; 1.2356x over previous
#include <cuda_runtime.h>
#include <math.h>
#include <stdint.h>

// ---------------------------------------------------------------------------
// FNO2d: B=16, Cin=5, S=128, W=64 ch, M=16 modes, D=4 layers, PAD=9 -> H=137
// All hot loops use Blackwell packed fp32 (fma.rn.f32x2) -- exact fp32 FMA
// at 2x issue density. Structure identical to the proven round-5 kernel.
// Packed values carried as unsigned long long (asm "l" constraint = s64/u64).
// ---------------------------------------------------------------------------

#define NB 16
#define NC 64
#define NH 137
#define NPIX (137*137)      // 18769
#define NM 16
#define NKX 32
#define ND 4
#define NBC (NB*NC)         // 1024

typedef unsigned long long u64t;

static __device__ __align__(16) float g_x[NBC*NPIX];       // field [bc][x*137+y]
static __device__ __align__(16) float g_a[NBC*NPIX];       // scratch
static __device__ __align__(16) float g_Y[NBC*NH*32];      // col DFT [bc][x][2m+p]
static __device__ __align__(16) float g_Z[512*2*NBC];      // spectrum [kk][p][bc]
static __device__ __align__(16) float g_S[NBC*1024];       // mixed [bo][kx][ky][p]
static __device__ __align__(16) float g_U[NBC*32*NH];      // inv-row [bo][2ky+p][x]
static __device__ __align__(16) float g_wm[ND*512*2*4096]; // [d][kk][p][i*64+o]
static __device__ __align__(16) float g_Ft[NH*32];         // fwd col [y][2m+p]
static __device__ __align__(16) float g_Gt[NH*64];         // fwd row [x][2kx+p]
static __device__ __align__(16) float g_Et[32*2*NH];       // inv row [kx][2x+p]
static __device__ __align__(16) float g_Tt[NH*32];         // inv col [y][2ky+p]

__device__ __forceinline__ float gelu_f(float v) {
    return 0.5f * v * (1.0f + erff(v * 0.70710678118654752440f));
}

// ---------------- packed fp32 (f32x2) primitives ---------------------------
__device__ __forceinline__ u64t ffma2(u64t a, u64t b, u64t c) {
    u64t d;
    asm("fma.rn.f32x2 %0, %1, %2, %3;" : "=l"(d) : "l"(a), "l"(b), "l"(c));
    return d;
}
__device__ __forceinline__ u64t pack2(float lo, float hi) {
    u64t d;
    asm("mov.b64 %0, {%1, %2};" : "=l"(d) : "f"(lo), "f"(hi));
    return d;
}
__device__ __forceinline__ void unpack2(u64t v, float& lo, float& hi) {
    asm("mov.b64 {%0, %1}, %2;" : "=f"(lo), "=f"(hi) : "l"(v));
}
#define ZERO2 0ULL

// ---------------- twiddle tables (double-precision sincos) -----------------
__global__ void k_tables() {
    int idx = blockIdx.x * blockDim.x + threadIdx.x;
    if (idx >= NKX * NH) return;
    int j = idx / NH, t = idx - j * NH;
    int gk = (j < NM) ? j : (NH - NKX + j);
    const double TWO_PI = 6.283185307179586476925286766559;
    double th = TWO_PI * (double)gk * (double)t / (double)NH;
    double s, c;
    sincos(th, &s, &c);
    g_Gt[t*64 + 2*j]     = (float)c;
    g_Gt[t*64 + 2*j + 1] = (float)(-s);
    g_Et[j*(2*NH) + 2*t]     = (float)c;
    g_Et[j*(2*NH) + 2*t + 1] = (float)(s);
    if (j < NM) {
        g_Ft[t*32 + 2*j]     = (float)c;
        g_Ft[t*32 + 2*j + 1] = (float)(-s);
        double wgt = ((j == 0) ? 1.0 : 2.0) / ((double)NH * (double)NH);
        g_Tt[t*32 + 2*j]     = (float)(wgt * c);
        g_Tt[t*32 + 2*j + 1] = (float)(-wgt * s);
    }
}

// ------------- spectral weight transpose: [d][p][i][o][mx][my] -> wm -------
__global__ void k_wt(const float* __restrict__ sw1, const float* __restrict__ sw2) {
    __shared__ float tile[32][33];
    int d   = blockIdx.z >> 2;
    int p   = (blockIdx.z >> 1) & 1;
    int arr = blockIdx.z & 1;
    const float* src = (arr ? sw2 : sw1) + (size_t)(d*2 + p) * 4096 * 256;
    int mxy = blockIdx.x * 32 + threadIdx.x;
    int io  = blockIdx.y * 32 + threadIdx.y;
    tile[threadIdx.y][threadIdx.x] = src[(size_t)io * 256 + mxy];
    __syncthreads();
    int mxy2 = blockIdx.x * 32 + threadIdx.y;
    int io2  = blockIdx.y * 32 + threadIdx.x;
    g_wm[((size_t)(d*512 + arr*256 + mxy2) * 2 + p) * 4096 + io2] = tile[threadIdx.x][threadIdx.y];
}

// ---------------- embed: concat grids, project 7->64, zero-pad -------------
__global__ __launch_bounds__(160) void k_embed(const float* __restrict__ xin,
                                               const float* __restrict__ pw,
                                               const float* __restrict__ pb) {
    __shared__ float spw[448];
    __shared__ float spb[64];
    int tid = threadIdx.x;
    for (int j = tid; j < 448; j += 160) spw[j] = pw[j];
    if (tid < 64) spb[tid] = pb[tid];
    __syncthreads();
    int b = blockIdx.y, x = blockIdx.x, y = tid;
    if (y >= NH) return;
    bool interior = (x < 128 && y < 128);
    float c[5]; float gx = 0.f, gy = 0.f;
    if (interior) {
        const float* src = xin + ((size_t)(b*5) * 128 + x) * 128 + y;
        #pragma unroll
        for (int i = 0; i < 5; i++) c[i] = src[(size_t)i * 128 * 128];
        const float step = 1.0f / 127.0f;
        gx = x * step; gy = y * step;
    }
    float* dst = g_x + ((size_t)(b*64) * NH + x) * NH + y;
    #pragma unroll 4
    for (int dd = 0; dd < 64; dd++) {
        float s = 0.f;
        if (interior) {
            s = spb[dd];
            #pragma unroll
            for (int i = 0; i < 5; i++) s += c[i] * spw[i*64 + dd];
            s += gx * spw[5*64 + dd] + gy * spw[6*64 + dd];
        }
        dst[(size_t)dd * NPIX] = s;
    }
}

// ------- forward column DFT over y: GEMM C[48x x 32] = X[48x137] F[137x32] ---
__global__ __launch_bounds__(128) void k_coldft() {
    __shared__ __align__(16) float sx[NH*49];   // [y][xr], scalar reads only
    int bc = blockIdx.y;
    int x0 = blockIdx.x * 48;
    int tid = threadIdx.x;
    const float* xin = g_x + (size_t)bc * NPIX;
    for (int idx = tid; idx < 48*NH; idx += 128) {
        int xr = idx / NH, y = idx - xr*NH;
        float v = (x0 + xr < NH) ? xin[(size_t)(x0+xr)*NH + y] : 0.f;
        sx[y*49 + xr] = v;
    }
    __syncthreads();
    int tx = tid & 7, ty = tid >> 3;
    int r0 = ty*3, c0 = tx*4;
    u64t a0x = ZERO2, a0y = ZERO2, a1x = ZERO2, a1y = ZERO2, a2x = ZERO2, a2y = ZERO2;
    #pragma unroll 2
    for (int y = 0; y < NH; y++) {
        ulonglong2 f2 = *(const ulonglong2*)&g_Ft[y*32 + c0];   // 4 twiddles, L1
        float v0 = sx[y*49 + r0];
        float v1 = sx[y*49 + r0 + 1];
        float v2 = sx[y*49 + r0 + 2];
        u64t p0 = pack2(v0, v0);
        u64t p1 = pack2(v1, v1);
        u64t p2 = pack2(v2, v2);
        a0x = ffma2(f2.x, p0, a0x); a0y = ffma2(f2.y, p0, a0y);
        a1x = ffma2(f2.x, p1, a1x); a1y = ffma2(f2.y, p1, a1y);
        a2x = ffma2(f2.x, p2, a2x); a2y = ffma2(f2.y, p2, a2y);
    }
    int r = x0 + r0;
    if (r < NH) {
        float* gy = &g_Y[((size_t)bc*NH + r)*32 + c0];
        unpack2(a0x, gy[0], gy[1]); unpack2(a0y, gy[2], gy[3]);
    }
    if (r + 1 < NH) {
        float* gy = &g_Y[((size_t)bc*NH + r + 1)*32 + c0];
        unpack2(a1x, gy[0], gy[1]); unpack2(a1y, gy[2], gy[3]);
    }
    if (r + 2 < NH) {
        float* gy = &g_Y[((size_t)bc*NH + r + 2)*32 + c0];
        unpack2(a2x, gy[0], gy[1]); unpack2(a2y, gy[2], gy[3]);
    }
}

// ------- forward row DFT over x: C[16ky x 32kx] complex, K=137 -------------
__global__ __launch_bounds__(128) void k_rowdft() {
    __shared__ __align__(16) float ys[NH*36];   // [x][2ky+p] pad 36
    int bc = blockIdx.x;
    int tid = threadIdx.x;
    for (int idx = tid; idx < NH*32; idx += 128) {
        int x = idx >> 5, c = idx & 31;
        ys[x*36 + c] = g_Y[((size_t)bc*NH + x)*32 + c];
    }
    __syncthreads();
    int tx = tid & 31;            // kx
    int ty = tid >> 5;            // ky group of 4
    u64t acc0 = ZERO2, acc1 = ZERO2, acc2 = ZERO2, acc3 = ZERO2;  // (re,im)
    #pragma unroll 2
    for (int x = 0; x < NH; x++) {
        const float4* yp = (const float4*)&ys[x*36 + ty*8];
        float4 yA = yp[0];
        float4 yB = yp[1];
        float gc = g_Gt[x*64 + 2*tx];
        float gs = g_Gt[x*64 + 2*tx + 1];
        u64t gP = pack2(gc, gs);
        u64t gN = pack2(-gs, gc);
        acc0 = ffma2(pack2(yA.x, yA.x), gP, ffma2(pack2(yA.y, yA.y), gN, acc0));
        acc1 = ffma2(pack2(yA.z, yA.z), gP, ffma2(pack2(yA.w, yA.w), gN, acc1));
        acc2 = ffma2(pack2(yB.x, yB.x), gP, ffma2(pack2(yB.y, yB.y), gN, acc2));
        acc3 = ffma2(pack2(yB.z, yB.z), gP, ffma2(pack2(yB.w, yB.w), gN, acc3));
    }
    u64t accs[4] = {acc0, acc1, acc2, acc3};
    #pragma unroll
    for (int j = 0; j < 4; j++) {
        int ky = ty*4 + j;
        size_t base = (size_t)((tx*16 + ky)*2)*NBC + bc;
        float re, im;
        unpack2(accs[j], re, im);
        g_Z[base]       = re;
        g_Z[base + NBC] = im;
    }
}

// ---------------- spectral channel mix: complex 64x64 per (kx,ky) ----------
__global__ __launch_bounds__(256) void k_mix(int d) {
    __shared__ float zr[1024], zi[1024];
    __shared__ float wr[4096], wi[4096];
    int kk = blockIdx.x;
    int tid = threadIdx.x;
    const float* wb = g_wm + ((size_t)(d*512 + kk) * 2) * 4096;
    for (int idx = tid; idx < 1024; idx += 256) {
        zr[idx] = g_Z[(size_t)(kk*2)*NBC + idx];
        zi[idx] = g_Z[(size_t)(kk*2 + 1)*NBC + idx];
    }
    for (int idx = tid; idx < 4096; idx += 256) {
        wr[idx] = wb[idx];
        wi[idx] = wb[4096 + idx];
    }
    __syncthreads();
    int kx = kk >> 4, ky = kk & 15;
    int o = tid & 63, bg = tid >> 6;
    u64t acc[4] = {ZERO2, ZERO2, ZERO2, ZERO2};   // (re,im) per batch
    #pragma unroll 2
    for (int i = 0; i < 64; i++) {
        float wrv = wr[i*64 + o], wiv = wi[i*64 + o];
        u64t wP = pack2(wrv, wiv);
        u64t wN = pack2(-wiv, wrv);
        #pragma unroll
        for (int jb = 0; jb < 4; jb++) {
            int b = bg*4 + jb;
            float a = zr[b*64 + i], bb = zi[b*64 + i];
            acc[jb] = ffma2(pack2(a, a), wP, ffma2(pack2(bb, bb), wN, acc[jb]));
        }
    }
    #pragma unroll
    for (int jb = 0; jb < 4; jb++) {
        size_t off = (size_t)((bg*4 + jb)*64 + o)*1024 + kx*32 + ky*2;
        *(u64t*)&g_S[off] = acc[jb];    // (re,im) adjacent, 8B aligned
    }
}

// ------- inverse row transform: per x, all 16 ky complex, K=32 kx ----------
__global__ __launch_bounds__(160) void k_invrow() {
    __shared__ __align__(16) float ss[1024];        // [kx][2ky+p]
    int bo = blockIdx.x, tid = threadIdx.x;
    for (int idx = tid; idx < 1024; idx += 160) ss[idx] = g_S[(size_t)bo*1024 + idx];
    __syncthreads();
    int x = tid;
    if (x >= NH) return;
    u64t acc[16];
    #pragma unroll
    for (int j = 0; j < 16; j++) acc[j] = ZERO2;
    for (int k = 0; k < 32; k++) {
        float2 e = *(const float2*)&g_Et[k*(2*NH) + 2*x];    // L1-resident
        u64t eP = pack2(e.x, e.y);
        u64t eN = pack2(-e.y, e.x);
        #pragma unroll
        for (int ky = 0; ky < 16; ky++) {
            float2 s = *(const float2*)&ss[k*32 + 2*ky];     // broadcast
            acc[ky] = ffma2(pack2(s.x, s.x), eP, ffma2(pack2(s.y, s.y), eN, acc[ky]));
        }
    }
    float* ub = g_U + (size_t)bo*32*NH;
    #pragma unroll
    for (int ky = 0; ky < 16; ky++) {
        float re, im;
        unpack2(acc[ky], re, im);
        ub[(2*ky)*NH + x]   = re;
        ub[(2*ky+1)*NH + x] = im;
    }
}

// ------- inverse column transform: u pairs in regs, lane=y stores ----------
__global__ __launch_bounds__(256) void k_invcol() {
    __shared__ __align__(16) float ts[NH*36];   // [y][2ky+p] pad 36
    int bo = blockIdx.y;
    int tid = threadIdx.x;
    for (int idx = tid; idx < NH*32; idx += 256) {
        int y = idx >> 5, c = idx & 31;
        ts[y*36 + c] = g_Tt[idx];
    }
    __syncthreads();
    int ly = tid & 31, xg = tid >> 5;
    int x = blockIdx.x * 8 + xg;
    if (x >= NH) return;
    const float* ub = g_U + (size_t)bo*32*NH;
    u64t u2[16];
    #pragma unroll
    for (int k = 0; k < 16; k++)
        u2[k] = pack2(ub[(2*k)*NH + x], ub[(2*k+1)*NH + x]);
    float* dst = g_a + (size_t)bo*NPIX + (size_t)x*NH;
    for (int y = ly; y < NH; y += 32) {
        const ulonglong2* t2 = (const ulonglong2*)&ts[y*36];
        u64t acc2 = ZERO2;
        #pragma unroll
        for (int k2 = 0; k2 < 8; k2++) {
            ulonglong2 t = t2[k2];
            acc2 = ffma2(u2[2*k2], t.x, acc2);
            acc2 = ffma2(u2[2*k2+1], t.y, acc2);
        }
        float lo, hi;
        unpack2(acc2, lo, hi);
        dst[y] = lo + hi;
    }
}

// ---------------- conv1x1 (mlp1) + exact gelu, in-place on g_a -------------
__global__ __launch_bounds__(256) void k_mlp1(const float* __restrict__ w,
                                              const float* __restrict__ bias, int d) {
    __shared__ __align__(16) float swT[4096];   // [i*64+o]
    __shared__ float sb[64];
    int tid = threadIdx.x;
    const float* wsrc = w + (size_t)d*4096;     // (o,i)
    for (int j = tid; j < 4096; j += 256) swT[j] = wsrc[(j & 63)*64 + (j >> 6)];
    if (tid < 64) sb[tid] = bias[d*64 + tid];
    __syncthreads();
    int b = blockIdx.y;
    int p = blockIdx.x*256 + tid;
    if (p >= NPIX) return;
    u64t acc2[32];
    #pragma unroll
    for (int j = 0; j < 32; j++) acc2[j] = pack2(sb[2*j], sb[2*j+1]);
    float* base = g_a + (size_t)b*64*NPIX + p;
    float a = base[0];
    for (int i = 0; i < 64; i++) {
        float an = (i < 63) ? base[(size_t)(i+1)*NPIX] : 0.0f;
        u64t av = pack2(a, a);
        const ulonglong2* w2 = (const ulonglong2*)(swT + i*64);
        #pragma unroll
        for (int q = 0; q < 16; q++) {
            ulonglong2 ww = w2[q];
            acc2[2*q]   = ffma2(ww.x, av, acc2[2*q]);
            acc2[2*q+1] = ffma2(ww.y, av, acc2[2*q+1]);
        }
        a = an;
    }
    #pragma unroll
    for (int j = 0; j < 32; j++) {
        float lo, hi;
        unpack2(acc2[j], lo, hi);
        base[(size_t)(2*j)*NPIX]   = gelu_f(lo);
        base[(size_t)(2*j+1)*NPIX] = gelu_f(hi);
    }
}

// -------- fused conv1x1 (mlp2) + skip conv (ww) + gelu, writes g_x ---------
__global__ __launch_bounds__(256) void k_mlp2(const float* __restrict__ w2p,
                                              const float* __restrict__ b2,
                                              const float* __restrict__ wwp,
                                              const float* __restrict__ wbp, int d) {
    __shared__ __align__(16) float s2[4096];
    __shared__ __align__(16) float s3[4096];
    __shared__ float sb[64];
    int tid = threadIdx.x;
    const float* w2s = w2p + (size_t)d*4096;
    const float* w3s = wwp + (size_t)d*4096;
    for (int j = tid; j < 4096; j += 256) {
        int o = j & 63, i = j >> 6;
        s2[j] = w2s[o*64 + i];
        s3[j] = w3s[o*64 + i];
    }
    if (tid < 64) sb[tid] = b2[d*64 + tid] + wbp[d*64 + tid];
    __syncthreads();
    int b = blockIdx.y;
    int p = blockIdx.x*256 + tid;
    if (p >= NPIX) return;
    u64t acc2[32];
    #pragma unroll
    for (int j = 0; j < 32; j++) acc2[j] = pack2(sb[2*j], sb[2*j+1]);
    const float* asrc = g_a + (size_t)b*64*NPIX + p;
    float* xsrc = g_x + (size_t)b*64*NPIX + p;
    float av = asrc[0], xv = xsrc[0];
    for (int i = 0; i < 64; i++) {
        float an = (i < 63) ? asrc[(size_t)(i+1)*NPIX] : 0.0f;
        float xn = (i < 63) ? xsrc[(size_t)(i+1)*NPIX] : 0.0f;
        u64t av2 = pack2(av, av);
        u64t xv2 = pack2(xv, xv);
        const ulonglong2* wa = (const ulonglong2*)(s2 + i*64);
        const ulonglong2* wb4 = (const ulonglong2*)(s3 + i*64);
        #pragma unroll
        for (int q = 0; q < 16; q++) {
            ulonglong2 wwa = wa[q];
            ulonglong2 wwb = wb4[q];
            acc2[2*q]   = ffma2(wwa.x, av2, ffma2(wwb.x, xv2, acc2[2*q]));
            acc2[2*q+1] = ffma2(wwa.y, av2, ffma2(wwb.y, xv2, acc2[2*q+1]));
        }
        av = an; xv = xn;
    }
    #pragma unroll
    for (int j = 0; j < 32; j++) {
        float lo, hi;
        unpack2(acc2[j], lo, hi);
        xsrc[(size_t)(2*j)*NPIX]   = gelu_f(lo);
        xsrc[(size_t)(2*j+1)*NPIX] = gelu_f(hi);
    }
}

// -------- head: crop + q1(64->256) + gelu + q2(256->1), two m-halves -------
__global__ __launch_bounds__(256) void k_head(const float* __restrict__ q1w,
                                              const float* __restrict__ q1b,
                                              const float* __restrict__ q2w,
                                              const float* __restrict__ q2b,
                                              float* __restrict__ out) {
    __shared__ __align__(16) float sw[8192];
    __shared__ float sb1[128], s2[128];
    int tid = threadIdx.x, b = blockIdx.y;
    int idx = blockIdx.x*256 + tid;
    int x = idx >> 7, y = idx & 127;
    const float* src = g_x + (size_t)b*64*NPIX + x*NH + y;
    u64t v2[32];
    #pragma unroll
    for (int i = 0; i < 32; i++)
        v2[i] = pack2(src[(size_t)(2*i)*NPIX], src[(size_t)(2*i+1)*NPIX]);
    float o = q2b[0];
    for (int half = 0; half < 2; half++) {
        __syncthreads();
        for (int j = tid; j < 8192; j += 256) sw[j] = q1w[half*8192 + j];
        if (tid < 128) { sb1[tid] = q1b[half*128 + tid]; s2[tid] = q2w[half*128 + tid]; }
        __syncthreads();
        for (int m = 0; m < 128; m++) {
            u64t h2a = ZERO2, h2b = ZERO2;
            const ulonglong2* w2 = (const ulonglong2*)(sw + m*64);
            #pragma unroll
            for (int q = 0; q < 16; q++) {
                ulonglong2 ww = w2[q];
                h2a = ffma2(ww.x, v2[2*q],   h2a);
                h2b = ffma2(ww.y, v2[2*q+1], h2b);
            }
            float l0, h0, l1, h1;
            unpack2(h2a, l0, h0);
            unpack2(h2b, l1, h1);
            o += s2[m] * gelu_f(sb1[m] + (l0 + h0) + (l1 + h1));
        }
    }
    out[(size_t)b*16384 + idx] = o;
}

// ---------------------------------------------------------------------------
extern "C" void kernel_launch(void* const* d_in, const int* in_sizes, int n_in,
                              void* d_out, int out_size) {
    const float* x   = (const float*)d_in[0];
    const float* p_w = (const float*)d_in[1];
    const float* p_b = (const float*)d_in[2];
    const float* sw1 = (const float*)d_in[3];
    const float* sw2 = (const float*)d_in[4];
    const float* m1w = (const float*)d_in[5];
    const float* m1b = (const float*)d_in[6];
    const float* m2w = (const float*)d_in[7];
    const float* m2b = (const float*)d_in[8];
    const float* wwp = (const float*)d_in[9];
    const float* wbp = (const float*)d_in[10];
    const float* q1w = (const float*)d_in[11];
    const float* q1b = (const float*)d_in[12];
    const float* q2w = (const float*)d_in[13];
    const float* q2b = (const float*)d_in[14];
    float* out = (float*)d_out;

    k_tables<<<18, 256>>>();
    k_wt<<<dim3(8, 128, 16), dim3(32, 32)>>>(sw1, sw2);
    k_embed<<<dim3(137, 16), 160>>>(x, p_w, p_b);

    const int mlpblocks = (NPIX + 255) / 256;
    for (int d = 0; d < ND; d++) {
        k_coldft<<<dim3(3, NBC), 128>>>();
        k_rowdft<<<NBC, 128>>>();
        k_mix<<<512, 256>>>(d);
        k_invrow<<<NBC, 160>>>();
        k_invcol<<<dim3(18, NBC), 256>>>();
        k_mlp1<<<dim3(mlpblocks, NB), 256>>>(m1w, m1b, d);
        k_mlp2<<<dim3(mlpblocks, NB), 256>>>(m2w, m2b, wwp, wbp, d);
    }

    k_head<<<dim3(64, NB), 256>>>(q1w, q1b, q2w, q2b, out);
}

// round 10
// speedup vs baseline: 1.3524x; 1.0945x over previous
#include <cuda_runtime.h>
#include <math.h>
#include <stdint.h>

// ---------------------------------------------------------------------------
// FNO2d: B=16, Cin=5, S=128, W=64 ch, M=16 modes, D=4 layers, PAD=9 -> H=137
// Packed fp32 (fma.rn.f32x2) everywhere; row-pair/batch-pair packing in the
// DFT kernels; invrow+invcol fused through shared memory.
// ---------------------------------------------------------------------------

#define NB 16
#define NC 64
#define NH 137
#define NPIX (137*137)      // 18769
#define NM 16
#define NKX 32
#define ND 4
#define NBC (NB*NC)         // 1024

typedef unsigned long long u64t;

static __device__ __align__(16) float g_x[NBC*NPIX];       // field [bc][x*137+y]
static __device__ __align__(16) float g_a[NBC*NPIX];       // scratch
static __device__ __align__(16) float g_Y[NBC*NH*32];      // col DFT [bc][x][2m+p]
static __device__ __align__(16) float g_Z[512*2*NBC];      // spectrum [kk][p][bc]
static __device__ __align__(16) float g_S[NBC*1024];       // mixed [bo][kx][ky][p]
static __device__ __align__(16) float g_wm[ND*512*2*4096]; // [d][kk][p][i*64+o]
static __device__ __align__(16) float g_Ft[NH*32];         // fwd col [y][2m+p]
static __device__ __align__(16) float g_Gt[NH*64];         // fwd row [x][2kx+p]
static __device__ __align__(16) float g_Et[32*2*NH];       // inv row [kx][2x+p]
static __device__ __align__(16) float g_Tt[NH*32];         // inv col [y][2ky+p]

__device__ __forceinline__ float gelu_f(float v) {
    return 0.5f * v * (1.0f + erff(v * 0.70710678118654752440f));
}

// ---------------- packed fp32 (f32x2) primitives ---------------------------
__device__ __forceinline__ u64t ffma2(u64t a, u64t b, u64t c) {
    u64t d;
    asm("fma.rn.f32x2 %0, %1, %2, %3;" : "=l"(d) : "l"(a), "l"(b), "l"(c));
    return d;
}
__device__ __forceinline__ u64t pack2(float lo, float hi) {
    u64t d;
    asm("mov.b64 %0, {%1, %2};" : "=l"(d) : "f"(lo), "f"(hi));
    return d;
}
__device__ __forceinline__ void unpack2(u64t v, float& lo, float& hi) {
    asm("mov.b64 {%0, %1}, %2;" : "=f"(lo), "=f"(hi) : "l"(v));
}
#define ZERO2 0ULL

// ---------------- twiddle tables (double-precision sincos) -----------------
__global__ void k_tables() {
    int idx = blockIdx.x * blockDim.x + threadIdx.x;
    if (idx >= NKX * NH) return;
    int j = idx / NH, t = idx - j * NH;
    int gk = (j < NM) ? j : (NH - NKX + j);
    const double TWO_PI = 6.283185307179586476925286766559;
    double th = TWO_PI * (double)gk * (double)t / (double)NH;
    double s, c;
    sincos(th, &s, &c);
    g_Gt[t*64 + 2*j]     = (float)c;
    g_Gt[t*64 + 2*j + 1] = (float)(-s);
    g_Et[j*(2*NH) + 2*t]     = (float)c;
    g_Et[j*(2*NH) + 2*t + 1] = (float)(s);
    if (j < NM) {
        g_Ft[t*32 + 2*j]     = (float)c;
        g_Ft[t*32 + 2*j + 1] = (float)(-s);
        double wgt = ((j == 0) ? 1.0 : 2.0) / ((double)NH * (double)NH);
        g_Tt[t*32 + 2*j]     = (float)(wgt * c);
        g_Tt[t*32 + 2*j + 1] = (float)(-wgt * s);
    }
}

// ------------- spectral weight transpose: [d][p][i][o][mx][my] -> wm -------
__global__ void k_wt(const float* __restrict__ sw1, const float* __restrict__ sw2) {
    __shared__ float tile[32][33];
    int d   = blockIdx.z >> 2;
    int p   = (blockIdx.z >> 1) & 1;
    int arr = blockIdx.z & 1;
    const float* src = (arr ? sw2 : sw1) + (size_t)(d*2 + p) * 4096 * 256;
    int mxy = blockIdx.x * 32 + threadIdx.x;
    int io  = blockIdx.y * 32 + threadIdx.y;
    tile[threadIdx.y][threadIdx.x] = src[(size_t)io * 256 + mxy];
    __syncthreads();
    int mxy2 = blockIdx.x * 32 + threadIdx.y;
    int io2  = blockIdx.y * 32 + threadIdx.x;
    g_wm[((size_t)(d*512 + arr*256 + mxy2) * 2 + p) * 4096 + io2] = tile[threadIdx.x][threadIdx.y];
}

// ---------------- embed: concat grids, project 7->64, zero-pad -------------
__global__ __launch_bounds__(160) void k_embed(const float* __restrict__ xin,
                                               const float* __restrict__ pw,
                                               const float* __restrict__ pb) {
    __shared__ float spw[448];
    __shared__ float spb[64];
    int tid = threadIdx.x;
    for (int j = tid; j < 448; j += 160) spw[j] = pw[j];
    if (tid < 64) spb[tid] = pb[tid];
    __syncthreads();
    int b = blockIdx.y, x = blockIdx.x, y = tid;
    if (y >= NH) return;
    bool interior = (x < 128 && y < 128);
    float c[5]; float gx = 0.f, gy = 0.f;
    if (interior) {
        const float* src = xin + ((size_t)(b*5) * 128 + x) * 128 + y;
        #pragma unroll
        for (int i = 0; i < 5; i++) c[i] = src[(size_t)i * 128 * 128];
        const float step = 1.0f / 127.0f;
        gx = x * step; gy = y * step;
    }
    float* dst = g_x + ((size_t)(b*64) * NH + x) * NH + y;
    #pragma unroll 4
    for (int dd = 0; dd < 64; dd++) {
        float s = 0.f;
        if (interior) {
            s = spb[dd];
            #pragma unroll
            for (int i = 0; i < 5; i++) s += c[i] * spw[i*64 + dd];
            s += gx * spw[5*64 + dd] + gy * spw[6*64 + dd];
        }
        dst[(size_t)dd * NPIX] = s;
    }
}

// ------- forward column DFT: 32-row tile, row-pair f32x2 packing -----------
__global__ __launch_bounds__(128) void k_coldft() {
    __shared__ __align__(16) float sx[NH*34];   // [y][xr] pitch 34 (even)
    int bc = blockIdx.y;
    int x0 = blockIdx.x * 32;
    int tid = threadIdx.x;
    const float* xin = g_x + (size_t)bc * NPIX;
    for (int idx = tid; idx < 32*NH; idx += 128) {
        int xr = idx / NH, y = idx - xr*NH;
        float v = (x0 + xr < NH) ? xin[(size_t)(x0+xr)*NH + y] : 0.f;
        sx[y*34 + xr] = v;
    }
    __syncthreads();
    int cg = tid & 15, rg = tid >> 4;     // 16 col-groups x 8 row-groups
    int c0 = cg*2, r0 = rg*4;             // 2 cols x 4 rows (2 pairs)
    u64t a00 = ZERO2, a01 = ZERO2, a10 = ZERO2, a11 = ZERO2;
    #pragma unroll 4
    for (int y = 0; y < NH; y++) {
        float2 f = *(const float2*)&g_Ft[y*32 + c0];   // L1-resident
        u64t fx = pack2(f.x, f.x), fy = pack2(f.y, f.y);
        const u64t* px = (const u64t*)&sx[y*34 + r0];  // even offset -> 8B ok
        u64t p0 = px[0], p1 = px[1];
        a00 = ffma2(p0, fx, a00); a01 = ffma2(p0, fy, a01);
        a10 = ffma2(p1, fx, a10); a11 = ffma2(p1, fy, a11);
    }
    int r = x0 + r0;
    float u0, u1, v0, v1;
    unpack2(a00, u0, u1); unpack2(a01, v0, v1);
    if (r < NH)     { size_t o = ((size_t)bc*NH + r    )*32 + c0; g_Y[o] = u0; g_Y[o+1] = v0; }
    if (r + 1 < NH) { size_t o = ((size_t)bc*NH + r + 1)*32 + c0; g_Y[o] = u1; g_Y[o+1] = v1; }
    unpack2(a10, u0, u1); unpack2(a11, v0, v1);
    if (r + 2 < NH) { size_t o = ((size_t)bc*NH + r + 2)*32 + c0; g_Y[o] = u0; g_Y[o+1] = v0; }
    if (r + 3 < NH) { size_t o = ((size_t)bc*NH + r + 3)*32 + c0; g_Y[o] = u1; g_Y[o+1] = v1; }
}

// ------- forward row DFT over x: C[16ky x 32kx] complex, K=137 -------------
__global__ __launch_bounds__(128) void k_rowdft() {
    __shared__ __align__(16) float ys[NH*36];   // [x][2ky+p] pad 36
    int bc = blockIdx.x;
    int tid = threadIdx.x;
    for (int idx = tid; idx < NH*32; idx += 128) {
        int x = idx >> 5, c = idx & 31;
        ys[x*36 + c] = g_Y[((size_t)bc*NH + x)*32 + c];
    }
    __syncthreads();
    int tx = tid & 31;            // kx
    int ty = tid >> 5;            // ky group of 4
    u64t acc0 = ZERO2, acc1 = ZERO2, acc2 = ZERO2, acc3 = ZERO2;  // (re,im)
    #pragma unroll 2
    for (int x = 0; x < NH; x++) {
        const float4* yp = (const float4*)&ys[x*36 + ty*8];
        float4 yA = yp[0];
        float4 yB = yp[1];
        float gc = g_Gt[x*64 + 2*tx];
        float gs = g_Gt[x*64 + 2*tx + 1];
        u64t gP = pack2(gc, gs);
        u64t gN = pack2(-gs, gc);
        acc0 = ffma2(pack2(yA.x, yA.x), gP, ffma2(pack2(yA.y, yA.y), gN, acc0));
        acc1 = ffma2(pack2(yA.z, yA.z), gP, ffma2(pack2(yA.w, yA.w), gN, acc1));
        acc2 = ffma2(pack2(yB.x, yB.x), gP, ffma2(pack2(yB.y, yB.y), gN, acc2));
        acc3 = ffma2(pack2(yB.z, yB.z), gP, ffma2(pack2(yB.w, yB.w), gN, acc3));
    }
    u64t accs[4] = {acc0, acc1, acc2, acc3};
    #pragma unroll
    for (int j = 0; j < 4; j++) {
        int ky = ty*4 + j;
        size_t base = (size_t)((tx*16 + ky)*2)*NBC + bc;
        float re, im;
        unpack2(accs[j], re, im);
        g_Z[base]       = re;
        g_Z[base + NBC] = im;
    }
}

// --- spectral channel mix: batch-pair f32x2 packing, Z transposed in smem ---
__global__ __launch_bounds__(256) void k_mix(int d) {
    __shared__ __align__(16) float zrt[64*18], zit[64*18];   // [chan][batch] pitch 18
    __shared__ float wr[4096], wi[4096];
    int kk = blockIdx.x;
    int tid = threadIdx.x;
    const float* wb = g_wm + ((size_t)(d*512 + kk) * 2) * 4096;
    for (int idx = tid; idx < 1024; idx += 256) {
        int chan = idx & 63, b = idx >> 6;
        zrt[chan*18 + b] = g_Z[(size_t)(kk*2)*NBC + idx];
        zit[chan*18 + b] = g_Z[(size_t)(kk*2 + 1)*NBC + idx];
    }
    for (int idx = tid; idx < 4096; idx += 256) {
        wr[idx] = wb[idx];
        wi[idx] = wb[4096 + idx];
    }
    __syncthreads();
    int kx = kk >> 4, ky = kk & 15;
    int o = tid & 63, bg = tid >> 6;      // 4 batches (2 pairs) per thread
    u64t accr0 = ZERO2, acci0 = ZERO2, accr1 = ZERO2, acci1 = ZERO2;
    #pragma unroll 2
    for (int i = 0; i < 64; i++) {
        float wrv = wr[i*64 + o], wiv = wi[i*64 + o];
        u64t w_r = pack2(wrv, wrv);
        u64t w_i = pack2(wiv, wiv);
        u64t w_n = pack2(-wiv, -wiv);
        const u64t* zr2 = (const u64t*)&zrt[i*18 + bg*4];   // even offsets
        const u64t* zi2 = (const u64t*)&zit[i*18 + bg*4];
        u64t a0 = zr2[0], a1 = zr2[1];
        u64t b0 = zi2[0], b1 = zi2[1];
        accr0 = ffma2(a0, w_r, ffma2(b0, w_n, accr0));
        acci0 = ffma2(a0, w_i, ffma2(b0, w_r, acci0));
        accr1 = ffma2(a1, w_r, ffma2(b1, w_n, accr1));
        acci1 = ffma2(a1, w_i, ffma2(b1, w_r, acci1));
    }
    float r0, r1, r2, r3, i0, i1, i2, i3;
    unpack2(accr0, r0, r1); unpack2(acci0, i0, i1);
    unpack2(accr1, r2, r3); unpack2(acci1, i2, i3);
    int bbase = bg*4;
    size_t tail = (size_t)kx*32 + ky*2;
    *(u64t*)&g_S[(size_t)((bbase+0)*64 + o)*1024 + tail] = pack2(r0, i0);
    *(u64t*)&g_S[(size_t)((bbase+1)*64 + o)*1024 + tail] = pack2(r1, i1);
    *(u64t*)&g_S[(size_t)((bbase+2)*64 + o)*1024 + tail] = pack2(r2, i2);
    *(u64t*)&g_S[(size_t)((bbase+3)*64 + o)*1024 + tail] = pack2(r3, i3);
}

// ------- fused inverse 2D: invrow (smem) + invcol, one block per bo --------
__global__ __launch_bounds__(256) void k_inv2d() {
    __shared__ float ss[1024];                   // [kx][2ky+p]
    __shared__ __align__(16) float su[NH*34];    // [x][2ky+p] pitch 34
    __shared__ __align__(16) float ts[NH*36];    // [y][2ky+p] pitch 36
    int bo = blockIdx.x, tid = threadIdx.x;
    for (int idx = tid; idx < 1024; idx += 256) ss[idx] = g_S[(size_t)bo*1024 + idx];
    for (int idx = tid; idx < NH*32; idx += 256) {
        int y = idx >> 5, c = idx & 31;
        ts[y*36 + c] = g_Tt[idx];
    }
    __syncthreads();
    // phase 1: inverse row transform -> su (2 threads per x, 8 ky each)
    if (tid < 2*NH) {
        int x = tid >> 1;
        int ky0 = (tid & 1) * 8;
        u64t acc[8];
        #pragma unroll
        for (int j = 0; j < 8; j++) acc[j] = ZERO2;
        for (int k = 0; k < 32; k++) {
            float2 e = *(const float2*)&g_Et[k*(2*NH) + 2*x];    // L1-resident
            u64t eP = pack2(e.x, e.y);
            u64t eN = pack2(-e.y, e.x);
            #pragma unroll
            for (int j = 0; j < 8; j++) {
                float2 s = *(const float2*)&ss[k*32 + 2*(ky0 + j)];   // broadcast
                acc[j] = ffma2(pack2(s.x, s.x), eP, ffma2(pack2(s.y, s.y), eN, acc[j]));
            }
        }
        u64t* up = (u64t*)&su[x*34 + 2*ky0];
        #pragma unroll
        for (int j = 0; j < 8; j++) up[j] = acc[j];   // (re,im) pairs
    }
    __syncthreads();
    // phase 2: inverse column transform, lane = y, coalesced stores
    int ly = tid & 31, xg = tid >> 5;
    float* dst = g_a + (size_t)bo*NPIX;
    for (int x = xg; x < NH; x += 8) {
        u64t u2[16];
        const u64t* up = (const u64t*)&su[x*34];
        #pragma unroll
        for (int k = 0; k < 16; k++) u2[k] = up[k];   // broadcast
        for (int y = ly; y < NH; y += 32) {
            const ulonglong2* t2 = (const ulonglong2*)&ts[y*36];
            u64t acc2 = ZERO2;
            #pragma unroll
            for (int k2 = 0; k2 < 8; k2++) {
                ulonglong2 t = t2[k2];
                acc2 = ffma2(u2[2*k2], t.x, acc2);
                acc2 = ffma2(u2[2*k2+1], t.y, acc2);
            }
            float lo, hi;
            unpack2(acc2, lo, hi);
            dst[(size_t)x*NH + y] = lo + hi;
        }
    }
}

// ---------------- conv1x1 (mlp1) + exact gelu, in-place on g_a -------------
__global__ __launch_bounds__(256) void k_mlp1(const float* __restrict__ w,
                                              const float* __restrict__ bias, int d) {
    __shared__ __align__(16) float swT[4096];   // [i*64+o]
    __shared__ float sb[64];
    int tid = threadIdx.x;
    const float* wsrc = w + (size_t)d*4096;     // (o,i)
    for (int j = tid; j < 4096; j += 256) swT[j] = wsrc[(j & 63)*64 + (j >> 6)];
    if (tid < 64) sb[tid] = bias[d*64 + tid];
    __syncthreads();
    int b = blockIdx.y;
    int p = blockIdx.x*256 + tid;
    if (p >= NPIX) return;
    u64t acc2[32];
    #pragma unroll
    for (int j = 0; j < 32; j++) acc2[j] = pack2(sb[2*j], sb[2*j+1]);
    float* base = g_a + (size_t)b*64*NPIX + p;
    float a = base[0];
    for (int i = 0; i < 64; i++) {
        float an = (i < 63) ? base[(size_t)(i+1)*NPIX] : 0.0f;
        u64t av = pack2(a, a);
        const ulonglong2* w2 = (const ulonglong2*)(swT + i*64);
        #pragma unroll
        for (int q = 0; q < 16; q++) {
            ulonglong2 ww = w2[q];
            acc2[2*q]   = ffma2(ww.x, av, acc2[2*q]);
            acc2[2*q+1] = ffma2(ww.y, av, acc2[2*q+1]);
        }
        a = an;
    }
    #pragma unroll
    for (int j = 0; j < 32; j++) {
        float lo, hi;
        unpack2(acc2[j], lo, hi);
        base[(size_t)(2*j)*NPIX]   = gelu_f(lo);
        base[(size_t)(2*j+1)*NPIX] = gelu_f(hi);
    }
}

// -------- fused conv1x1 (mlp2) + skip conv (ww) + gelu, writes g_x ---------
__global__ __launch_bounds__(256) void k_mlp2(const float* __restrict__ w2p,
                                              const float* __restrict__ b2,
                                              const float* __restrict__ wwp,
                                              const float* __restrict__ wbp, int d) {
    __shared__ __align__(16) float s2[4096];
    __shared__ __align__(16) float s3[4096];
    __shared__ float sb[64];
    int tid = threadIdx.x;
    const float* w2s = w2p + (size_t)d*4096;
    const float* w3s = wwp + (size_t)d*4096;
    for (int j = tid; j < 4096; j += 256) {
        int o = j & 63, i = j >> 6;
        s2[j] = w2s[o*64 + i];
        s3[j] = w3s[o*64 + i];
    }
    if (tid < 64) sb[tid] = b2[d*64 + tid] + wbp[d*64 + tid];
    __syncthreads();
    int b = blockIdx.y;
    int p = blockIdx.x*256 + tid;
    if (p >= NPIX) return;
    u64t acc2[32];
    #pragma unroll
    for (int j = 0; j < 32; j++) acc2[j] = pack2(sb[2*j], sb[2*j+1]);
    const float* asrc = g_a + (size_t)b*64*NPIX + p;
    float* xsrc = g_x + (size_t)b*64*NPIX + p;
    float av = asrc[0], xv = xsrc[0];
    for (int i = 0; i < 64; i++) {
        float an = (i < 63) ? asrc[(size_t)(i+1)*NPIX] : 0.0f;
        float xn = (i < 63) ? xsrc[(size_t)(i+1)*NPIX] : 0.0f;
        u64t av2 = pack2(av, av);
        u64t xv2 = pack2(xv, xv);
        const ulonglong2* wa = (const ulonglong2*)(s2 + i*64);
        const ulonglong2* wb4 = (const ulonglong2*)(s3 + i*64);
        #pragma unroll
        for (int q = 0; q < 16; q++) {
            ulonglong2 wwa = wa[q];
            ulonglong2 wwb = wb4[q];
            acc2[2*q]   = ffma2(wwa.x, av2, ffma2(wwb.x, xv2, acc2[2*q]));
            acc2[2*q+1] = ffma2(wwa.y, av2, ffma2(wwb.y, xv2, acc2[2*q+1]));
        }
        av = an; xv = xn;
    }
    #pragma unroll
    for (int j = 0; j < 32; j++) {
        float lo, hi;
        unpack2(acc2[j], lo, hi);
        xsrc[(size_t)(2*j)*NPIX]   = gelu_f(lo);
        xsrc[(size_t)(2*j+1)*NPIX] = gelu_f(hi);
    }
}

// -------- head: crop + q1(64->256) + gelu + q2(256->1), two m-halves -------
__global__ __launch_bounds__(256) void k_head(const float* __restrict__ q1w,
                                              const float* __restrict__ q1b,
                                              const float* __restrict__ q2w,
                                              const float* __restrict__ q2b,
                                              float* __restrict__ out) {
    __shared__ __align__(16) float sw[8192];
    __shared__ float sb1[128], s2[128];
    int tid = threadIdx.x, b = blockIdx.y;
    int idx = blockIdx.x*256 + tid;
    int x = idx >> 7, y = idx & 127;
    const float* src = g_x + (size_t)b*64*NPIX + x*NH + y;
    u64t v2[32];
    #pragma unroll
    for (int i = 0; i < 32; i++)
        v2[i] = pack2(src[(size_t)(2*i)*NPIX], src[(size_t)(2*i+1)*NPIX]);
    float o = q2b[0];
    for (int half = 0; half < 2; half++) {
        __syncthreads();
        for (int j = tid; j < 8192; j += 256) sw[j] = q1w[half*8192 + j];
        if (tid < 128) { sb1[tid] = q1b[half*128 + tid]; s2[tid] = q2w[half*128 + tid]; }
        __syncthreads();
        for (int m = 0; m < 128; m++) {
            u64t h2a = ZERO2, h2b = ZERO2;
            const ulonglong2* w2 = (const ulonglong2*)(sw + m*64);
            #pragma unroll
            for (int q = 0; q < 16; q++) {
                ulonglong2 ww = w2[q];
                h2a = ffma2(ww.x, v2[2*q],   h2a);
                h2b = ffma2(ww.y, v2[2*q+1], h2b);
            }
            float l0, h0, l1, h1;
            unpack2(h2a, l0, h0);
            unpack2(h2b, l1, h1);
            o += s2[m] * gelu_f(sb1[m] + (l0 + h0) + (l1 + h1));
        }
    }
    out[(size_t)b*16384 + idx] = o;
}

// ---------------------------------------------------------------------------
extern "C" void kernel_launch(void* const* d_in, const int* in_sizes, int n_in,
                              void* d_out, int out_size) {
    const float* x   = (const float*)d_in[0];
    const float* p_w = (const float*)d_in[1];
    const float* p_b = (const float*)d_in[2];
    const float* sw1 = (const float*)d_in[3];
    const float* sw2 = (const float*)d_in[4];
    const float* m1w = (const float*)d_in[5];
    const float* m1b = (const float*)d_in[6];
    const float* m2w = (const float*)d_in[7];
    const float* m2b = (const float*)d_in[8];
    const float* wwp = (const float*)d_in[9];
    const float* wbp = (const float*)d_in[10];
    const float* q1w = (const float*)d_in[11];
    const float* q1b = (const float*)d_in[12];
    const float* q2w = (const float*)d_in[13];
    const float* q2b = (const float*)d_in[14];
    float* out = (float*)d_out;

    k_tables<<<18, 256>>>();
    k_wt<<<dim3(8, 128, 16), dim3(32, 32)>>>(sw1, sw2);
    k_embed<<<dim3(137, 16), 160>>>(x, p_w, p_b);

    const int mlpblocks = (NPIX + 255) / 256;
    for (int d = 0; d < ND; d++) {
        k_coldft<<<dim3(5, NBC), 128>>>();
        k_rowdft<<<NBC, 128>>>();
        k_mix<<<512, 256>>>(d);
        k_inv2d<<<NBC, 256>>>();
        k_mlp1<<<dim3(mlpblocks, NB), 256>>>(m1w, m1b, d);
        k_mlp2<<<dim3(mlpblocks, NB), 256>>>(m2w, m2b, wwp, wbp, d);
    }

    k_head<<<dim3(64, NB), 256>>>(q1w, q1b, q2w, q2b, out);
}